// round 12
// baseline (speedup 1.0000x reference)
#include <cuda_runtime.h>
#include <cuda_fp16.h>
#include <cstdint>

// Problem-size constants (sized for this dataset)
#define MAX_N      150016
#define MAX_E      4194304
#define EMBD       64
#define ALLW       256   // 4 * EMB concatenated width

// -------- scratch (device globals: no allocations allowed) ----------------
__device__ float  g_side [(size_t)MAX_N * EMBD];    // 38.4 MB
__device__ __half g_ego16[(size_t)MAX_N * EMBD];    // 19.2 MB (recurrence state)
__device__ float  g_alle [(size_t)MAX_N * ALLW];    // 153.6 MB
__device__ int    g_deg [MAX_N];    // zero at load; re-zeroed by k_fill each call
__device__ int    g_row [MAX_N + 1];
__device__ int    g_cur [MAX_N];
__device__ int2   g_edge[MAX_E];                    // (src, w-bits) 32 MB

// ---------------------------------------------------------------------------
// combo launch 0: init ego16/alle rows AND edge histogram (independent work).
// g_deg is guaranteed zero on entry (static zero-init on first call; k_fill
// re-zeroes it at the end of every call).
// ---------------------------------------------------------------------------
__global__ void k_init_hist(const float4* __restrict__ ue, const float4* __restrict__ ie,
                            const int* __restrict__ dst,
                            int n_user, int N, int nE)
{
    size_t t = (size_t)blockIdx.x * blockDim.x + threadIdx.x;

    size_t total = (size_t)N * 16;
    if (t < total) {
        int row = (int)(t >> 4);
        int c   = (int)(t & 15);
        float4 v = (row < n_user) ? ue[(size_t)row * 16 + c]
                                  : ie[(size_t)(row - n_user) * 16 + c];
        reinterpret_cast<float4*>(g_alle)[(size_t)row * 64 + c] = v;  // cols 0..63
        __half2 h0 = __floats2half2_rn(v.x, v.y);
        __half2 h1 = __floats2half2_rn(v.z, v.w);
        reinterpret_cast<uint2*>(g_ego16)[t] =
            make_uint2(*reinterpret_cast<unsigned*>(&h0),
                       *reinterpret_cast<unsigned*>(&h1));
    }
    if (t < (size_t)nE)
        atomicAdd(&g_deg[dst[t]], 1);
}

// ---------------------------------------------------------------------------
// launch 1: fused scan. Each block sums its predecessor range of g_deg
// (600 KB array, L2-resident; total redundant volume ~44 MB) to get its
// exclusive offset, then scans its own 1024 nodes and writes row/cur.
// ---------------------------------------------------------------------------
__global__ void k_scan_fused(int nE, int N)
{
    __shared__ int s[256];
    int tid = threadIdx.x;
    int blk = blockIdx.x;

    // predecessor sum
    int pre = 0;
    int limit = blk * 1024;
    for (int i = tid; i < limit; i += 256) pre += g_deg[i];
    s[tid] = pre;
    __syncthreads();
    for (int off = 128; off > 0; off >>= 1) {
        if (tid < off) s[tid] += s[tid + off];
        __syncthreads();
    }
    int block_off = s[0];
    __syncthreads();

    // own 1024-element scan (4 per thread)
    int base = blk * 1024 + tid * 4;
    int v[4]; int ts = 0;
    #pragma unroll
    for (int k = 0; k < 4; k++) {
        v[k] = (base + k < N) ? g_deg[base + k] : 0;
        ts += v[k];
    }
    s[tid] = ts;
    __syncthreads();
    for (int off = 1; off < 256; off <<= 1) {
        int t = (tid >= off) ? s[tid - off] : 0;
        __syncthreads();
        s[tid] += t;
        __syncthreads();
    }
    int excl = s[tid] - ts + block_off;
    #pragma unroll
    for (int k = 0; k < 4; k++) {
        if (base + k < N) {
            g_row[base + k] = excl;
            g_cur[base + k] = excl;
            excl += v[k];
        }
    }
    if (blk == 0 && tid == 0) g_row[N] = nE;
}

// ---------------------------------------------------------------------------
// launch 2: fill CSR edge array; also re-zero g_deg for the next call
// (deg's last reader was k_scan_fused; no race here).
// ---------------------------------------------------------------------------
__global__ void k_fill(const int* __restrict__ src, const int* __restrict__ dst,
                       const float* __restrict__ w, int nE, int N)
{
    int e = blockIdx.x * blockDim.x + threadIdx.x;
    if (e < N) g_deg[e] = 0;
    if (e >= nE) return;
    int d   = dst[e];
    int pos = atomicAdd(&g_cur[d], 1);
    g_edge[pos] = make_int2(src[e], __float_as_int(w[e]));
}

// ---------------------------------------------------------------------------
// launch 3 (ncu target): aggregate
//   side[n] = sum_{e in CSR row n} w_e * ego16[src_e]  (fp32 accum)
// ONE WARP per node: 2 edges/iter, unroll 8 (16 gathers in flight/warp),
// lanes [0..15] edge e, [16..31] edge e+1; shfl_xor(16) reduce; no atomics.
// ---------------------------------------------------------------------------
__global__ void __launch_bounds__(256)
k_aggregate(int N)
{
    int node = (int)(((size_t)blockIdx.x * blockDim.x + threadIdx.x) >> 5);
    if (node >= N) return;
    int lane = threadIdx.x & 31;
    int half = lane >> 4;
    int c    = lane & 15;

    int beg = g_row[node];
    int end = g_row[node + 1];
    const uint2* ebase = reinterpret_cast<const uint2*>(g_ego16);

    float4 acc = make_float4(0.f, 0.f, 0.f, 0.f);
    #pragma unroll 8
    for (int e = beg + half; e < end; e += 2) {
        int2  sw = g_edge[e];
        float w  = __int_as_float(sw.y);
        uint2 r  = __ldg(&ebase[(size_t)sw.x * 16 + c]);
        __half2 h0 = *reinterpret_cast<__half2*>(&r.x);
        __half2 h1 = *reinterpret_cast<__half2*>(&r.y);
        float2 f0 = __half22float2(h0);
        float2 f1 = __half22float2(h1);
        acc.x += w * f0.x; acc.y += w * f0.y;
        acc.z += w * f1.x; acc.w += w * f1.y;
    }
    acc.x += __shfl_xor_sync(0xFFFFFFFFu, acc.x, 16);
    acc.y += __shfl_xor_sync(0xFFFFFFFFu, acc.y, 16);
    acc.z += __shfl_xor_sync(0xFFFFFFFFu, acc.z, 16);
    acc.w += __shfl_xor_sync(0xFFFFFFFFu, acc.w, 16);
    if (half == 0)
        *reinterpret_cast<float4*>(&g_side[(size_t)node * EMBD + c * 4]) = acc;
}

// ---------------------------------------------------------------------------
// transform: fused dual-GEMM + bias + leaky_relu + row-norm, packed f32x2 FMA.
// TWO nodes per thread (weight LDS amortized). ego read from fp16 mirror.
//   sum_e = side @ Wgc + bgc ; bi_e = (ego*side) @ Wbi + bbi
//   new ego (fp16 mirror) = leaky_relu(sum_e + bi_e, 0.2)
//   all_e[:, out_col : +64] = new_ego / max(||new_ego||, 1e-12)   (fp32)
// ---------------------------------------------------------------------------
#define FMA2(d, a, b) asm("fma.rn.f32x2 %0, %1, %2, %0;" : "+l"(d) : "l"(a), "l"(b))

__device__ __forceinline__ unsigned long long pack2(float lo, float hi)
{
    unsigned long long r;
    asm("mov.b64 %0, {%1, %2};" : "=l"(r)
        : "r"(__float_as_uint(lo)), "r"(__float_as_uint(hi)));
    return r;
}
__device__ __forceinline__ void unpack2(unsigned long long v, float& lo, float& hi)
{
    unsigned int a, b;
    asm("mov.b64 {%0, %1}, %2;" : "=r"(a), "=r"(b) : "l"(v));
    lo = __uint_as_float(a); hi = __uint_as_float(b);
}

__device__ __forceinline__ void epilogue_node(unsigned long long* acc2, int n, int out_col)
{
    float sumsq = 0.f;
    #pragma unroll
    for (int j2 = 0; j2 < 32; j2++) {
        float lo, hi;
        unpack2(acc2[j2], lo, hi);
        lo = (lo >= 0.f) ? lo : 0.2f * lo;
        hi = (hi >= 0.f) ? hi : 0.2f * hi;
        acc2[j2] = pack2(lo, hi);
        sumsq += lo * lo + hi * hi;
    }
    float inv = 1.0f / fmaxf(sqrtf(sumsq), 1e-12f);

    float* ap  = &g_alle[(size_t)n * ALLW + out_col];
    uint2* e16 = reinterpret_cast<uint2*>(&g_ego16[(size_t)n * EMBD]);
    #pragma unroll
    for (int j4 = 0; j4 < 16; j4++) {
        float a0, a1, a2, a3;
        unpack2(acc2[2 * j4    ], a0, a1);
        unpack2(acc2[2 * j4 + 1], a2, a3);
        __half2 h0 = __floats2half2_rn(a0, a1);
        __half2 h1 = __floats2half2_rn(a2, a3);
        e16[j4] = make_uint2(*reinterpret_cast<unsigned*>(&h0),
                             *reinterpret_cast<unsigned*>(&h1));
        float4 v = make_float4(a0 * inv, a1 * inv, a2 * inv, a3 * inv);
        *reinterpret_cast<float4*>(&ap[j4 * 4]) = v;      // normalized slice (fp32)
    }
}

__global__ void __launch_bounds__(128)
k_transform(const float* __restrict__ Wgc, const float* __restrict__ bgc,
            const float* __restrict__ Wbi, const float* __restrict__ bbi,
            int N, int out_col)
{
    __shared__ __align__(16) float sWgc[EMBD * EMBD];
    __shared__ __align__(16) float sWbi[EMBD * EMBD];
    __shared__ float sB[EMBD];

    for (int t = threadIdx.x; t < EMBD * EMBD; t += blockDim.x) {
        sWgc[t] = Wgc[t];
        sWbi[t] = Wbi[t];
    }
    if (threadIdx.x < EMBD) sB[threadIdx.x] = bgc[threadIdx.x] + bbi[threadIdx.x];
    __syncthreads();

    int n0 = (blockIdx.x * blockDim.x + threadIdx.x) * 2;
    if (n0 >= N) return;
    int n1 = (n0 + 1 < N) ? n0 + 1 : n0;   // clamp: duplicate work, same result

    const float* spA = &g_side[(size_t)n0 * EMBD];
    const float* spB = &g_side[(size_t)n1 * EMBD];
    const uint2* e16 = reinterpret_cast<const uint2*>(g_ego16);

    unsigned long long accA[32], accB[32];
    #pragma unroll
    for (int j2 = 0; j2 < 32; j2++) {
        unsigned long long b2 = pack2(sB[2 * j2], sB[2 * j2 + 1]);
        accA[j2] = b2; accB[j2] = b2;
    }

    #pragma unroll 2
    for (int i4 = 0; i4 < 16; i4++) {
        float4 sA  = __ldg(reinterpret_cast<const float4*>(&spA[i4 * 4]));
        float4 sBv = __ldg(reinterpret_cast<const float4*>(&spB[i4 * 4]));
        uint2  rA  = __ldg(&e16[(size_t)n0 * 16 + i4]);
        uint2  rB  = __ldg(&e16[(size_t)n1 * 16 + i4]);
        float2 eA0 = __half22float2(*reinterpret_cast<__half2*>(&rA.x));
        float2 eA1 = __half22float2(*reinterpret_cast<__half2*>(&rA.y));
        float2 eB0 = __half22float2(*reinterpret_cast<__half2*>(&rB.x));
        float2 eB1 = __half22float2(*reinterpret_cast<__half2*>(&rB.y));
        float ssA[4] = {sA.x, sA.y, sA.z, sA.w};
        float ppA[4] = {sA.x * eA0.x, sA.y * eA0.y, sA.z * eA1.x, sA.w * eA1.y};
        float ssB[4] = {sBv.x, sBv.y, sBv.z, sBv.w};
        float ppB[4] = {sBv.x * eB0.x, sBv.y * eB0.y, sBv.z * eB1.x, sBv.w * eB1.y};
        #pragma unroll
        for (int sub = 0; sub < 4; sub++) {
            int i = i4 * 4 + sub;
            unsigned long long s2A = pack2(ssA[sub], ssA[sub]);
            unsigned long long p2A = pack2(ppA[sub], ppA[sub]);
            unsigned long long s2B = pack2(ssB[sub], ssB[sub]);
            unsigned long long p2B = pack2(ppB[sub], ppB[sub]);
            const ulonglong2* wg = reinterpret_cast<const ulonglong2*>(&sWgc[i * EMBD]);
            const ulonglong2* wb = reinterpret_cast<const ulonglong2*>(&sWbi[i * EMBD]);
            #pragma unroll
            for (int q = 0; q < 16; q++) {
                ulonglong2 a = wg[q];
                ulonglong2 b = wb[q];
                FMA2(accA[q * 2    ], s2A, a.x);
                FMA2(accA[q * 2 + 1], s2A, a.y);
                FMA2(accA[q * 2    ], p2A, b.x);
                FMA2(accA[q * 2 + 1], p2A, b.y);
                FMA2(accB[q * 2    ], s2B, a.x);
                FMA2(accB[q * 2 + 1], s2B, a.y);
                FMA2(accB[q * 2    ], p2B, b.x);
                FMA2(accB[q * 2 + 1], p2B, b.y);
            }
        }
    }

    epilogue_node(accA, n0, out_col);
    if (n1 != n0) epilogue_node(accB, n1, out_col);
}

// ---------------------------------------------------------------------------
// final gather: out = [all_e[users], all_e[n_user+pos], all_e[n_user+neg]]
// Index arrays may be int32 or int64 (JAX x64 ambiguity) -> detect on device.
// ---------------------------------------------------------------------------
__device__ __forceinline__ int detect_is64(const int* w, int count)
{
    int n = (count < 64) ? count : 64;
    int f = 0;
    for (int k = 1; k < 2 * n; k += 2) f |= w[k];
    return (f == 0) ? 1 : 0;
}

__global__ void k_gather(const void* __restrict__ users, const void* __restrict__ pos,
                         const void* __restrict__ neg, float* __restrict__ out,
                         int n_user, int batch)
{
    __shared__ int sIs64[3];
    if (threadIdx.x < 3) {
        const void* a = (threadIdx.x == 0) ? users : (threadIdx.x == 1) ? pos : neg;
        sIs64[threadIdx.x] = detect_is64(reinterpret_cast<const int*>(a), batch);
    }
    __syncthreads();

    int row = blockIdx.x * 4 + (threadIdx.x >> 6);   // 4 rows / 256-thread block
    int c   = threadIdx.x & 63;
    if (row >= 3 * batch) return;
    int grp = row / batch;
    int idx = row - grp * batch;
    const void* a = (grp == 0) ? users : (grp == 1) ? pos : neg;
    long long node;
    if (sIs64[grp]) node = reinterpret_cast<const long long*>(a)[idx];
    else            node = (long long)reinterpret_cast<const int*>(a)[idx];
    if (grp > 0) node += n_user;

    float4 v = *reinterpret_cast<const float4*>(&g_alle[(size_t)node * ALLW + c * 4]);
    *reinterpret_cast<float4*>(&out[(size_t)row * ALLW + c * 4]) = v;
}

// ---------------------------------------------------------------------------
extern "C" void kernel_launch(void* const* d_in, const int* in_sizes, int n_in,
                              void* d_out, int out_size)
{
    const float* user_emb = (const float*)d_in[0];
    const float* item_emb = (const float*)d_in[1];
    const float* W_gc     = (const float*)d_in[2];
    const float* b_gc     = (const float*)d_in[3];
    const float* W_bi     = (const float*)d_in[4];
    const float* b_bi     = (const float*)d_in[5];
    const float* edge_w   = (const float*)d_in[6];
    const int*   edge_src = (const int*)  d_in[7];
    const int*   edge_dst = (const int*)  d_in[8];
    const void*  users    = d_in[9];
    const void*  pos      = d_in[10];
    const void*  neg      = d_in[11];

    int n_user = in_sizes[0] / EMBD;
    int n_item = in_sizes[1] / EMBD;
    int N      = n_user + n_item;
    int layers = in_sizes[2] / (EMBD * EMBD);
    int nE     = in_sizes[6];
    int batch  = in_sizes[9];

    // launch 0: init + histogram (deg pre-zeroed invariant)
    {
        size_t work = (size_t)N * 16;
        if ((size_t)nE > work) work = (size_t)nE;
        int grid = (int)((work + 255) / 256);
        k_init_hist<<<grid, 256>>>((const float4*)user_emb, (const float4*)item_emb,
                                   edge_dst, n_user, N, nE);
    }

    // launch 1: fused scan -> row/cur
    int nblk = (N + 1023) / 1024;
    k_scan_fused<<<nblk, 256>>>(nE, N);

    // launch 2: fill CSR (+ re-zero deg for next call)
    k_fill<<<(nE + 255) / 256, 256>>>(edge_src, edge_dst, edge_w, nE, N);

    // launch 3 = first k_aggregate  (global launch #5 -> ncu -s 5 -c 1 target)
    for (int k = 0; k < layers; k++) {
        {
            size_t threads = (size_t)N * 32;
            int grid = (int)((threads + 255) / 256);
            k_aggregate<<<grid, 256>>>(N);
        }
        {
            int pairs = (N + 1) / 2;
            int grid  = (pairs + 127) / 128;
            k_transform<<<grid, 128>>>(W_gc + (size_t)k * EMBD * EMBD,
                                       b_gc + (size_t)k * EMBD,
                                       W_bi + (size_t)k * EMBD * EMBD,
                                       b_bi + (size_t)k * EMBD,
                                       N, EMBD * (k + 1));
        }
    }

    // final gather
    {
        int rows = 3 * batch;
        int grid = (rows + 3) / 4;
        k_gather<<<grid, 256>>>(users, pos, neg, (float*)d_out, n_user, batch);
    }
}